// round 4
// baseline (speedup 1.0000x reference)
#include <cuda_runtime.h>
#include <math.h>

// Problem constants
#define NB        128      // persistent blocks (<= 148 SMs, all resident)
#define NT        256
#define T_STEPS   512
#define BATCH     32
#define IN_SZ     512
#define OUT_SZ    512
#define LHID      512      // per-direction hidden
#define KTOT      1536     // 1024 (inp) + 512 (h)
#define KG        4        // k-split groups per block
#define KPG       384      // K per group
#define KC        64       // k-chunk
#define NCH       6        // chunks per group (384/64)
#define PADK      68       // KC + 4 (odd float4 stride -> conflict-free LDS)
#define HN_BASE   (BATCH * T_STEPS * OUT_SZ)   // 8,388,608

// Persistent state (device globals; no allocation allowed)
__device__ float g_hbuf[2][2][2][BATCH][LHID];  // [parity][layer][dir][b][u]
__device__ float g_c[2][2][BATCH][LHID];        // [layer][dir][b][u]
__device__ float g_prev[BATCH][OUT_SZ];
__device__ unsigned int g_count = 0;
__device__ volatile unsigned int g_gen = 0;

__device__ __forceinline__ void grid_sync() {
    __syncthreads();
    if (threadIdx.x == 0) {
        __threadfence();
        unsigned gen = g_gen;
        if (atomicAdd(&g_count, 1u) == NB - 1) {
            g_count = 0;
            __threadfence();
            g_gen = gen + 1;
        } else {
            while (g_gen == gen) { }
        }
        __threadfence();
    }
    __syncthreads();
}

__device__ __forceinline__ float sigm(float x) { return 1.0f / (1.0f + expf(-x)); }

// smem layout (union of layer-phase and FC-phase views)
// layer phase: w_s[KG][32][PADK] | x_s[KG][32][PADK] | red[KG][32][33] | tot[32][33] | bias[32]
// FC phase   : hs[32][1028] | fcred[256]
#define SMEM_FLOATS 33152
#define SMEM_BYTES  (SMEM_FLOATS * 4)

__global__ void __launch_bounds__(NT, 1)
ae_kernel(const float* __restrict__ x_in,
          const float* __restrict__ W_ih, const float* __restrict__ W_hh,
          const float* __restrict__ b_ih, const float* __restrict__ b_hh,
          const float* __restrict__ W_fc, const float* __restrict__ b_fc,
          float* __restrict__ out)
{
    extern __shared__ float sm[];
    const int tid = threadIdx.x;
    const int bid = blockIdx.x;

    // ---- init state to zero (read at t=0) ----
    {
        float* h0 = &g_hbuf[0][0][0][0][0];
        for (int e = bid * NT + tid; e < 2 * 2 * BATCH * LHID; e += NB * NT) h0[e] = 0.0f;
        float* c0 = &g_c[0][0][0][0];
        for (int e = bid * NT + tid; e < 2 * 2 * BATCH * LHID; e += NB * NT) c0[e] = 0.0f;
        float* p0 = &g_prev[0][0];
        for (int e = bid * NT + tid; e < BATCH * OUT_SZ; e += NB * NT) p0[e] = 0.0f;
    }
    grid_sync();

    // layer-phase block mapping: 128 blocks = 2 dirs x 64 unit-groups of 8 units
    const int d   = bid >> 6;
    const int u0  = (bid & 63) << 3;
    const int kg  = tid >> 6;        // k-group 0..3
    const int t64 = tid & 63;
    const int trow = t64 >> 3;       // 0..7  (rows trow, trow+8, +16, +24)
    const int tcol = t64 & 7;        // 0..7  (cols tcol, tcol+8, +16, +24)

    float* w_s    = sm;                               // KG*32*PADK = 8704
    float* x_s    = w_s + KG * 32 * PADK;             // 8704
    float* red    = x_s + KG * 32 * PADK;             // KG*32*33 = 4224
    float* tot    = red + KG * 32 * 33;               // 32*33 = 1056
    float* bias_s = tot + 32 * 33;                    // 32
    float* hs     = sm;                               // FC: 32*1028 = 32896
    float* fcred  = sm + 32 * 1028;                   // FC: 256

    for (int t = 0; t < T_STEPS; ++t) {
        const int rp = t & 1;        // read parity of recurrent h
        const int wp = rp ^ 1;       // write parity

        for (int l = 0; l < 2; ++l) {
            // preload combined bias for this block's 32 gate rows
            if (tid < 32) {
                int grow = ((tid >> 3) << 9) + u0 + (tid & 7);
                int bo = (l * 2 + d) * 2048 + grow;
                bias_s[tid] = b_ih[bo] + b_hh[bo];
            }
            float acc[4][4] = {};
            const float* wih_base = W_ih + (size_t)(l * 2 + d) * 2048 * 1024;
            const float* whh_base = W_hh + (size_t)(l * 2 + d) * 2048 * 512;

            for (int ch = 0; ch < NCH; ++ch) {
                const int k0 = kg * KPG + ch * KC;     // region boundaries align to 64
                // stage weights: 32 rows x 64 k (this kg), 8 float4 per thread
                #pragma unroll
                for (int p = 0; p < 8; ++p) {
                    int idx = p * 64 + t64;
                    int r = idx >> 4, kq = idx & 15;
                    int grow = ((r >> 3) << 9) + u0 + (r & 7);
                    float4 v;
                    if (k0 < 1024)
                        v = *(const float4*)(wih_base + (size_t)grow * 1024 + k0 + kq * 4);
                    else
                        v = *(const float4*)(whh_base + (size_t)grow * 512 + (k0 - 1024) + kq * 4);
                    *(float4*)&w_s[(kg * 32 + r) * PADK + kq * 4] = v;
                }
                // stage activations: 32 batch x 64 k
                #pragma unroll
                for (int p = 0; p < 8; ++p) {
                    int idx = p * 64 + t64;
                    int c = idx >> 4, kq = idx & 15;
                    int k = k0 + kq * 4;
                    const float* src;
                    if (l == 0) {
                        if (k < 512)        src = x_in + ((size_t)c * T_STEPS + t) * IN_SZ + k;
                        else if (k < 1024)  src = &g_prev[c][k - 512];
                        else                src = &g_hbuf[rp][0][d][c][k - 1024];
                    } else {
                        if (k < 512)        src = &g_hbuf[wp][0][0][c][k];
                        else if (k < 1024)  src = &g_hbuf[wp][0][1][c][k - 512];
                        else                src = &g_hbuf[rp][1][d][c][k - 1024];
                    }
                    *(float4*)&x_s[(kg * 32 + c) * PADK + kq * 4] = *(const float4*)src;
                }
                __syncthreads();
                // 4x4 micro-tile, k-vectorized x4
                #pragma unroll
                for (int kq = 0; kq < 16; ++kq) {
                    float4 xv[4], wv[4];
                    #pragma unroll
                    for (int j = 0; j < 4; ++j)
                        xv[j] = *(float4*)&x_s[(kg * 32 + tcol + 8 * j) * PADK + kq * 4];
                    #pragma unroll
                    for (int i = 0; i < 4; ++i)
                        wv[i] = *(float4*)&w_s[(kg * 32 + trow + 8 * i) * PADK + kq * 4];
                    #pragma unroll
                    for (int i = 0; i < 4; ++i)
                        #pragma unroll
                        for (int j = 0; j < 4; ++j) {
                            acc[i][j] += wv[i].x * xv[j].x;
                            acc[i][j] += wv[i].y * xv[j].y;
                            acc[i][j] += wv[i].z * xv[j].z;
                            acc[i][j] += wv[i].w * xv[j].w;
                        }
                }
                __syncthreads();
            }
            // reduce 4 k-partials
            #pragma unroll
            for (int i = 0; i < 4; ++i)
                #pragma unroll
                for (int j = 0; j < 4; ++j)
                    red[(kg * 32 + trow + 8 * i) * 33 + (tcol + 8 * j)] = acc[i][j];
            __syncthreads();
            for (int e = tid; e < 1024; e += NT) {
                int r = e >> 5, c = e & 31;
                float s = red[(0 * 32 + r) * 33 + c] + red[(1 * 32 + r) * 33 + c]
                        + red[(2 * 32 + r) * 33 + c] + red[(3 * 32 + r) * 33 + c];
                tot[r * 33 + c] = s + bias_s[r];
            }
            __syncthreads();
            // elementwise LSTM cell update: 256 threads = 32 batch x 8 units
            {
                int c = tid >> 3, j = tid & 7;
                float gi = tot[(0 * 8 + j) * 33 + c];
                float gf = tot[(1 * 8 + j) * 33 + c];
                float gg = tot[(2 * 8 + j) * 33 + c];
                float go = tot[(3 * 8 + j) * 33 + c];
                float cold = g_c[l][d][c][u0 + j];
                float cn = sigm(gf) * cold + sigm(gi) * tanhf(gg);
                float hn = sigm(go) * tanhf(cn);
                g_c[l][d][c][u0 + j] = cn;
                g_hbuf[wp][l][d][c][u0 + j] = hn;
            }
            grid_sync();
        }

        // ---- FC phase: pred = h1cat @ W_fc^T + b_fc ----
        {
            // stage h1cat [32 x 1024] in smem (coalesced)
            for (int idx = tid; idx < 8192; idx += NT) {
                int c = idx >> 8, kq = idx & 255;
                int k = kq * 4;
                const float* src = (k < 512) ? &g_hbuf[wp][1][0][c][k]
                                             : &g_hbuf[wp][1][1][c][k - 512];
                *(float4*)&hs[c * 1028 + k] = *(const float4*)src;
            }
            __syncthreads();
            const int o0 = bid << 2;                 // 4 output rows per block
            const int kh = tid >> 7, t2 = tid & 127;
            const int o = o0 + (t2 >> 5), c = t2 & 31;
            float a = 0.0f;
            const float* wrow = W_fc + (size_t)o * 1024 + kh * 512;
            const float* xrow = hs + c * 1028 + kh * 512;
            #pragma unroll 8
            for (int q = 0; q < 128; ++q) {
                float4 wv = *(const float4*)(wrow + q * 4);
                float4 xv = *(const float4*)(xrow + q * 4);
                a += wv.x * xv.x; a += wv.y * xv.y;
                a += wv.z * xv.z; a += wv.w * xv.w;
            }
            fcred[kh * 128 + t2] = a;
            __syncthreads();
            if (tid < 128) {
                int c2 = tid >> 2, oo = tid & 3;
                int idx = oo * 32 + c2;
                float v = fcred[idx] + fcred[128 + idx] + b_fc[o0 + oo];
                out[((size_t)c2 * T_STEPS + t) * OUT_SZ + o0 + oo] = v;
                g_prev[c2][o0 + oo] = v;
            }
            grid_sync();
        }
    }

    // ---- final h_n, c_n (last write parity = (T)&1 = 0) ----
    {
        const float* hsrc = &g_hbuf[0][0][0][0][0];   // [l][d][b][u] flat = h_n layout
        const float* csrc = &g_c[0][0][0][0];
        for (int e = bid * NT + tid; e < 2 * 2 * BATCH * LHID; e += NB * NT) {
            out[HN_BASE + e] = hsrc[e];
            out[HN_BASE + 65536 + e] = csrc[e];
        }
    }
}

extern "C" void kernel_launch(void* const* d_in, const int* in_sizes, int n_in,
                              void* d_out, int out_size) {
    const float* input_seq = (const float*)d_in[0];
    // d_in[1] = input_lengths (all == T, unused by the reference path)
    const float* W_ih = (const float*)d_in[2];
    const float* W_hh = (const float*)d_in[3];
    const float* b_ih = (const float*)d_in[4];
    const float* b_hh = (const float*)d_in[5];
    const float* W_fc = (const float*)d_in[6];
    const float* b_fc = (const float*)d_in[7];
    float* out = (float*)d_out;

    cudaFuncSetAttribute(ae_kernel, cudaFuncAttributeMaxDynamicSharedMemorySize, SMEM_BYTES);
    ae_kernel<<<NB, NT, SMEM_BYTES>>>(input_seq, W_ih, W_hh, b_ih, b_hh, W_fc, b_fc, out);
}

// round 6
// speedup vs baseline: 1.7266x; 1.7266x over previous
#include <cuda_runtime.h>
#include <math.h>

// Problem constants
#define NB        128      // persistent blocks (<= 148 SMs, all resident)
#define NT        256
#define T_STEPS   512
#define BATCH     32
#define IN_SZ     512
#define OUT_SZ    512
#define LHID      512      // per-direction hidden
#define NG        8        // k-groups (one warp each)
#define KPG       192      // K per group (1536/8)
#define KC        32       // k per chunk per group
#define NCH       6        // chunks (192/32)
#define PADK      36       // KC + 4 ; 36*4B = 144 ≡ 16 mod 128 -> conflict-free LDS.128
#define WBUF      (NG * 32 * PADK)             // 9216 floats per buffer
#define HN_BASE   (BATCH * T_STEPS * OUT_SZ)   // 8,388,608

// Persistent state (device globals; no allocation allowed)
__device__ float g_hbuf[2][2][2][BATCH][LHID];  // [parity][layer][dir][b][u]
__device__ float g_c[2][2][BATCH][LHID];        // [layer][dir][b][u]
__device__ float g_prev[BATCH][OUT_SZ];
__device__ unsigned int g_count = 0;
__device__ volatile unsigned int g_gen = 0;

__device__ __forceinline__ void grid_sync() {
    __threadfence();           // publish this thread's global writes
    __syncthreads();
    if (threadIdx.x == 0) {
        unsigned gen = g_gen;
        if (atomicAdd(&g_count, 1u) == NB - 1) {
            g_count = 0;
            __threadfence();
            g_gen = gen + 1;
        } else {
            while (g_gen == gen) { }
        }
        __threadfence();
    }
    __syncthreads();
}

__device__ __forceinline__ float sigm(float x) { return 1.0f / (1.0f + expf(-x)); }

// cp.async helpers (LDGSTS, L2-only path: no L1 staleness on recurrent state)
__device__ __forceinline__ void cp_async16(void* smem_dst, const void* gsrc) {
    unsigned saddr = (unsigned)__cvta_generic_to_shared(smem_dst);
    asm volatile("cp.async.cg.shared.global [%0], [%1], 16;\n" :: "r"(saddr), "l"(gsrc));
}
__device__ __forceinline__ void cp_commit() {
    asm volatile("cp.async.commit_group;\n");
}
template <int N> __device__ __forceinline__ void cp_wait() {
    asm volatile("cp.async.wait_group %0;\n" :: "n"(N));
}

// smem layout (floats):
//   layer phase: w_s[2][WBUF] | x_s[2][WBUF] | red[NG*32*33] | tot[32*33] | bias[32]
//                18432        | 18432        | 8448          | 1056      | 32   = 46400
//   FC phase   : hs[32*1028]=32896 | wfc[4096] | fcred[256]   (overlaps w_s/x_s)
#define SMEM_FLOATS 46400
#define SMEM_BYTES  (SMEM_FLOATS * 4)

__global__ void __launch_bounds__(NT, 1)
ae_kernel(const float* __restrict__ x_in,
          const float* __restrict__ W_ih, const float* __restrict__ W_hh,
          const float* __restrict__ b_ih, const float* __restrict__ b_hh,
          const float* __restrict__ W_fc, const float* __restrict__ b_fc,
          float* __restrict__ out)
{
    extern __shared__ float sm[];
    const int tid = threadIdx.x;
    const int bid = blockIdx.x;

    // ---- init state to zero (read at t=0) ----
    {
        float* h0 = &g_hbuf[0][0][0][0][0];
        for (int e = bid * NT + tid; e < 2 * 2 * BATCH * LHID; e += NB * NT) h0[e] = 0.0f;
        float* c0 = &g_c[0][0][0][0];
        for (int e = bid * NT + tid; e < 2 * 2 * BATCH * LHID; e += NB * NT) c0[e] = 0.0f;
        float* p0 = &g_prev[0][0];
        for (int e = bid * NT + tid; e < BATCH * OUT_SZ; e += NB * NT) p0[e] = 0.0f;
    }
    grid_sync();

    // layer-phase block mapping: 128 blocks = 2 dirs x 64 unit-groups of 8 units
    const int d    = bid >> 6;
    const int u0   = (bid & 63) << 3;
    const int grp  = tid >> 5;        // k-group == warp id, 0..7
    const int t32  = tid & 31;        // lane
    const int trow4 = t32 >> 3;       // 0..3 : owns rows trow4*8 .. trow4*8+7
    const int tcol  = t32 & 7;        // 0..7 : owns cols tcol, tcol+8, +16, +24

    float* w_s    = sm;                    // 2 * WBUF = 18432
    float* x_s    = sm + 2 * WBUF;         // 18432
    float* red    = sm + 4 * WBUF;         // NG*32*33 = 8448
    float* tot    = red + NG * 32 * 33;    // 1056
    float* bias_s = tot + 32 * 33;         // 32
    float* hs     = sm;                    // FC: 32*1028 = 32896
    float* wfc_s  = sm + 32 * 1028;        // FC: 4096
    float* fcred  = wfc_s + 4096;          // FC: 256

    for (int t = 0; t < T_STEPS; ++t) {
        const int rp = t & 1;        // read parity of recurrent h
        const int wp = rp ^ 1;       // write parity

        for (int l = 0; l < 2; ++l) {
            // preload combined bias for this block's 32 gate rows
            if (tid < 32) {
                int grow = ((tid >> 3) << 9) + u0 + (tid & 7);
                int bo = (l * 2 + d) * 2048 + grow;
                bias_s[tid] = b_ih[bo] + b_hh[bo];
            }
            const float* wih_base = W_ih + (size_t)(l * 2 + d) * 2048 * 1024;
            const float* whh_base = W_hh + (size_t)(l * 2 + d) * 2048 * 512;

            // ---- staging lambda (cp.async of one chunk into a buffer pair) ----
            auto stage = [&](int ch, float* wbuf, float* xbuf) {
                const int k0 = grp * KPG + ch * KC;   // 32-aligned, never straddles regions
                // weights: 32 rows x 32 k for this group -> 256 float4, 8 per lane
                #pragma unroll
                for (int p = 0; p < 8; ++p) {
                    int idx = p * 32 + t32;
                    int r = idx >> 3, kq4 = idx & 7;
                    int grow = ((r >> 3) << 9) + u0 + (r & 7);
                    const float* src = (k0 < 1024)
                        ? wih_base + (size_t)grow * 1024 + k0 + kq4 * 4
                        : whh_base + (size_t)grow * 512 + (k0 - 1024) + kq4 * 4;
                    cp_async16(&wbuf[(grp * 32 + r) * PADK + kq4 * 4], src);
                }
                // activations: 32 batch x 32 k
                #pragma unroll
                for (int p = 0; p < 8; ++p) {
                    int idx = p * 32 + t32;
                    int c = idx >> 3, kq4 = idx & 7;
                    int k = k0 + kq4 * 4;
                    const float* src;
                    if (l == 0) {
                        if (k < 512)        src = x_in + ((size_t)c * T_STEPS + t) * IN_SZ + k;
                        else if (k < 1024)  src = &g_prev[c][k - 512];
                        else                src = &g_hbuf[rp][0][d][c][k - 1024];
                    } else {
                        if (k < 512)        src = &g_hbuf[wp][0][0][c][k];
                        else if (k < 1024)  src = &g_hbuf[wp][0][1][c][k - 512];
                        else                src = &g_hbuf[rp][1][d][c][k - 1024];
                    }
                    cp_async16(&xbuf[(grp * 32 + c) * PADK + kq4 * 4], src);
                }
            };

            float acc[8][4];
            #pragma unroll
            for (int i = 0; i < 8; ++i)
                #pragma unroll
                for (int j = 0; j < 4; ++j) acc[i][j] = 0.0f;

            // prologue: chunk 0 -> buffer 0
            stage(0, w_s, x_s);
            cp_commit();

            for (int ch = 0; ch < NCH; ++ch) {
                if (ch + 1 < NCH) {
                    stage(ch + 1, w_s + ((ch + 1) & 1) * WBUF, x_s + ((ch + 1) & 1) * WBUF);
                    cp_commit();
                    cp_wait<1>();     // chunk ch complete, ch+1 in flight
                } else {
                    cp_wait<0>();
                }
                __syncthreads();

                const float* wb = w_s + (ch & 1) * WBUF;
                const float* xb = x_s + (ch & 1) * WBUF;
                #pragma unroll
                for (int kq = 0; kq < 8; ++kq) {
                    float4 xv[4];
                    #pragma unroll
                    for (int j = 0; j < 4; ++j)
                        xv[j] = *(const float4*)&xb[(grp * 32 + tcol + 8 * j) * PADK + kq * 4];
                    #pragma unroll
                    for (int i = 0; i < 8; ++i) {
                        float4 wv = *(const float4*)&wb[(grp * 32 + trow4 * 8 + i) * PADK + kq * 4];
                        #pragma unroll
                        for (int j = 0; j < 4; ++j) {
                            acc[i][j] += wv.x * xv[j].x;
                            acc[i][j] += wv.y * xv[j].y;
                            acc[i][j] += wv.z * xv[j].z;
                            acc[i][j] += wv.w * xv[j].w;
                        }
                    }
                }
                __syncthreads();   // buffer (ch&1) free for reuse at ch+2
            }

            // write 8 k-partials
            #pragma unroll
            for (int i = 0; i < 8; ++i)
                #pragma unroll
                for (int j = 0; j < 4; ++j)
                    red[(grp * 32 + trow4 * 8 + i) * 33 + (tcol + 8 * j)] = acc[i][j];
            __syncthreads();
            // reduce partials + bias
            for (int e = tid; e < 1024; e += NT) {
                int r = e >> 5, c = e & 31;
                float s = 0.0f;
                #pragma unroll
                for (int g = 0; g < NG; ++g)
                    s += red[(g * 32 + r) * 33 + c];
                tot[r * 33 + c] = s + bias_s[r];
            }
            __syncthreads();
            // elementwise LSTM cell update: 256 threads = 32 batch x 8 units
            {
                int c = tid >> 3, j = tid & 7;
                float gi = tot[(0 * 8 + j) * 33 + c];
                float gf = tot[(1 * 8 + j) * 33 + c];
                float gg = tot[(2 * 8 + j) * 33 + c];
                float go = tot[(3 * 8 + j) * 33 + c];
                float cold = g_c[l][d][c][u0 + j];
                float cn = sigm(gf) * cold + sigm(gi) * tanhf(gg);
                float hn = sigm(go) * tanhf(cn);
                g_c[l][d][c][u0 + j] = cn;
                g_hbuf[wp][l][d][c][u0 + j] = hn;
            }
            grid_sync();
        }

        // ---- FC phase: pred = h1cat @ W_fc^T + b_fc ----
        {
            // stage h1cat [32 x 1024] and this block's 4 W_fc rows via cp.async
            #pragma unroll 8
            for (int p = 0; p < 32; ++p) {
                int idx = p * 256 + tid;           // 8192 float4
                int c = idx >> 8, kq = idx & 255;
                int k = kq * 4;
                const float* src = (k < 512) ? &g_hbuf[wp][1][0][c][k]
                                             : &g_hbuf[wp][1][1][c][k - 512];
                cp_async16(&hs[c * 1028 + k], src);
            }
            #pragma unroll
            for (int p = 0; p < 4; ++p) {
                int i2 = p * 256 + tid;            // 1024 float4
                cp_async16(&wfc_s[i2 * 4], W_fc + ((size_t)(bid << 2)) * 1024 + i2 * 4);
            }
            cp_commit();
            cp_wait<0>();
            __syncthreads();

            const int o0 = bid << 2;               // 4 output rows per block
            const int kh = tid >> 7, t2 = tid & 127;
            const int ol = t2 >> 5, c = t2 & 31;
            float a = 0.0f;
            const float* wrow = wfc_s + ol * 1024 + kh * 512;
            const float* xrow = hs + c * 1028 + kh * 512;
            #pragma unroll 8
            for (int q = 0; q < 128; ++q) {
                float4 wv = *(const float4*)(wrow + q * 4);
                float4 xv = *(const float4*)(xrow + q * 4);
                a += wv.x * xv.x; a += wv.y * xv.y;
                a += wv.z * xv.z; a += wv.w * xv.w;
            }
            fcred[kh * 128 + t2] = a;
            __syncthreads();
            if (tid < 128) {
                int c2 = tid >> 2, oo = tid & 3;
                int idx = oo * 32 + c2;
                float v = fcred[idx] + fcred[128 + idx] + b_fc[o0 + oo];
                out[((size_t)c2 * T_STEPS + t) * OUT_SZ + o0 + oo] = v;
                g_prev[c2][o0 + oo] = v;
            }
            grid_sync();
        }
    }

    // ---- final h_n, c_n (last write parity = T&1 = 0) ----
    {
        const float* hsrc = &g_hbuf[0][0][0][0][0];   // [l][d][b][u] flat = h_n layout
        const float* csrc = &g_c[0][0][0][0];
        for (int e = bid * NT + tid; e < 2 * 2 * BATCH * LHID; e += NB * NT) {
            out[HN_BASE + e] = hsrc[e];
            out[HN_BASE + 65536 + e] = csrc[e];
        }
    }
}

extern "C" void kernel_launch(void* const* d_in, const int* in_sizes, int n_in,
                              void* d_out, int out_size) {
    const float* input_seq = (const float*)d_in[0];
    // d_in[1] = input_lengths (all == T, unused by the reference path)
    const float* W_ih = (const float*)d_in[2];
    const float* W_hh = (const float*)d_in[3];
    const float* b_ih = (const float*)d_in[4];
    const float* b_hh = (const float*)d_in[5];
    const float* W_fc = (const float*)d_in[6];
    const float* b_fc = (const float*)d_in[7];
    float* out = (float*)d_out;

    cudaFuncSetAttribute(ae_kernel, cudaFuncAttributeMaxDynamicSharedMemorySize, SMEM_BYTES);
    ae_kernel<<<NB, NT, SMEM_BYTES>>>(input_seq, W_ih, W_hh, b_ih, b_hh, W_fc, b_fc, out);
}